// round 5
// baseline (speedup 1.0000x reference)
#include <cuda_runtime.h>
#include <cuda_bf16.h>
#include <math.h>
#include <stdint.h>

// Problem dims
#define LNUM 9
#define BDIM 8
#define SAQ 512
#define SBK 512
#define EDIM 1024
#define HNUM 16
#define DHEAD 64
#define FDIM 4096
#define MROWS (BDIM*SAQ)          // 4096

typedef __nv_bfloat16 bf16;
typedef __nv_bfloat162 bf162;

// ---------------- scratch (device globals) ----------------------------------
__device__ float g_A  [MROWS*EDIM];
__device__ float g_A1 [MROWS*EDIM];
__device__ float g_TMP[MROWS*EDIM];
__device__ float g_V  [MROWS*EDIM];
__device__ float g_PART[1024];

__device__ bf16 g_Ahi [MROWS*EDIM],  g_Alo [MROWS*EDIM];
__device__ bf16 g_A1hi[MROWS*EDIM],  g_A1lo[MROWS*EDIM];
__device__ bf16 g_Dhi [BDIM*SBK*EDIM], g_Dlo [BDIM*SBK*EDIM];
__device__ bf16 g_Qhi [MROWS*EDIM],  g_Qlo [MROWS*EDIM];
__device__ bf16 g_Khi [MROWS*EDIM],  g_Klo [MROWS*EDIM];
__device__ bf16 g_VThi[EDIM*MROWS],  g_VTlo[EDIM*MROWS];
__device__ bf16 g_CThi[MROWS*EDIM],  g_CTlo[MROWS*EDIM];
__device__ bf16 g_MIDhi[(long)MROWS*FDIM], g_MIDlo[(long)MROWS*FDIM];
__device__ bf16 g_IPWhi[LNUM*3*EDIM*EDIM], g_IPWlo[LNUM*3*EDIM*EDIM];
__device__ bf16 g_OWhi [LNUM*EDIM*EDIM],   g_OWlo [LNUM*EDIM*EDIM];
__device__ bf16 g_W1hi [(long)LNUM*FDIM*EDIM], g_W1lo[(long)LNUM*FDIM*EDIM];
__device__ bf16 g_W2hi [(long)LNUM*EDIM*FDIM], g_W2lo[(long)LNUM*EDIM*FDIM];

// ---------------- helpers ----------------------------------------------------
__device__ __forceinline__ void split2(float v, bf16& h, bf16& l) {
    h = __float2bfloat16(v);
    l = __float2bfloat16(v - __bfloat162float(h));
}
__device__ __forceinline__ void pack_hl(float x, float y, unsigned& ph, unsigned& pl) {
    bf16 xh, xl, yh, yl;
    split2(x, xh, xl); split2(y, yh, yl);
    ph = (uint32_t)__bfloat16_as_ushort(xh) | ((uint32_t)__bfloat16_as_ushort(yh) << 16);
    pl = (uint32_t)__bfloat16_as_ushort(xl) | ((uint32_t)__bfloat16_as_ushort(yl) << 16);
}

__device__ __forceinline__ uint32_t smem_u32(const void* p) {
    uint32_t a;
    asm("{ .reg .u64 t; cvta.to.shared.u64 t, %1; cvt.u32.u64 %0, t; }"
        : "=r"(a) : "l"(p));
    return a;
}

#define CPA16(dst, src) \
    asm volatile("cp.async.cg.shared.global [%0], [%1], 16;" :: "r"(dst), "l"(src))
#define CPA_COMMIT() asm volatile("cp.async.commit_group;" ::: "memory")
#define CPA_WAIT1()  asm volatile("cp.async.wait_group 1;" ::: "memory")
#define CPA_WAIT0()  asm volatile("cp.async.wait_group 0;" ::: "memory")

__global__ void copy_f(const float* __restrict__ src, float* __restrict__ dst, int n) {
    int i = blockIdx.x * blockDim.x + threadIdx.x;
    if (i < n) dst[i] = src[i];
}

__global__ void split_f(const float* __restrict__ src, bf16* __restrict__ hi,
                        bf16* __restrict__ lo, int n) {
    int i = blockIdx.x * blockDim.x + threadIdx.x;
    if (i < n) { bf16 h, l; split2(src[i], h, l); hi[i] = h; lo[i] = l; }
}

// V [4096][1024] f32 -> VT [1024][4096] split bf16
__global__ void transpose_split(const float* __restrict__ V,
                                bf16* __restrict__ VThi, bf16* __restrict__ VTlo) {
    __shared__ float t[32][33];
    int bx = blockIdx.x * 32, by = blockIdx.y * 32;
    int tx = threadIdx.x, ty = threadIdx.y;
#pragma unroll
    for (int i = 0; i < 4; i++)
        t[ty + i*8][tx] = V[(long)(by + ty + i*8) * EDIM + bx + tx];
    __syncthreads();
#pragma unroll
    for (int i = 0; i < 4; i++) {
        float v = t[tx][ty + i*8];
        bf16 h, l; split2(v, h, l);
        long o = (long)(bx + ty + i*8) * MROWS + by + tx;
        VThi[o] = h; VTlo[o] = l;
    }
}

__device__ __forceinline__ void mma16816(float* d, const unsigned* a, const unsigned* b) {
    asm volatile(
        "mma.sync.aligned.m16n8k16.row.col.f32.bf16.bf16.f32 "
        "{%0,%1,%2,%3},{%4,%5,%6,%7},{%8,%9},{%0,%1,%2,%3};"
        : "+f"(d[0]), "+f"(d[1]), "+f"(d[2]), "+f"(d[3])
        : "r"(a[0]), "r"(a[1]), "r"(a[2]), "r"(a[3]), "r"(b[0]), "r"(b[1]));
}

// ---------------- bf16x3 warp-MMA GEMM (TN), cp.async double-buffered --------
template<int BN>
__global__ void __launch_bounds__(256, 2) gemm_bf3(
    const bf16* __restrict__ Ahi_g, const bf16* __restrict__ Alo_g,
    const bf16* __restrict__ Bhi_g, const bf16* __restrict__ Blo_g,
    const float* __restrict__ bias,
    float* __restrict__ Cf, bf16* __restrict__ Chi, bf16* __restrict__ Clo,
    int K, int lda, int ldb, int ldc,
    long sAb, long sAh, long sBb, long sBh, long sCb, long sCh, int nH,
    float alpha, int mode, int relu)
{
    constexpr int KS  = 40;
    constexpr int AST = 128 * KS;
    constexpr int BST = BN * KS;
    constexpr int STG = 2 * AST + 2 * BST;
    constexpr int NT  = BN / 16;

    extern __shared__ bf16 sm[];
    uint32_t smb = smem_u32(sm);

    int bz = blockIdx.z;
    int bb = bz / nH, hh = bz % nH;
    const bf16* Ah = Ahi_g + bb * sAb + hh * sAh;
    const bf16* Al = Alo_g + bb * sAb + hh * sAh;
    const bf16* Bh = Bhi_g + bb * sBb + hh * sBh;
    const bf16* Bl = Blo_g + bb * sBb + hh * sBh;
    long cbase = bb * sCb + hh * sCh;

    int bm = blockIdx.y * 128, bn = blockIdx.x * BN;
    int tid = threadIdx.x;
    int wid = tid >> 5, lane = tid & 31;
    int wm = wid & 3, wn = wid >> 2;
    int mb = wm * 32, nb = wn * (BN / 2);
    int lr = lane >> 2, lc = (lane & 3) * 2;

    float acc[2][NT][4];
#pragma unroll
    for (int i = 0; i < 2; i++)
#pragma unroll
        for (int j = 0; j < NT; j++)
#pragma unroll
            for (int q = 0; q < 4; q++) acc[i][j][q] = 0.f;

    auto load_stage = [&](int s, int kt) {
        uint32_t sb = smb + (uint32_t)s * (STG * 2);
#pragma unroll 4
        for (int i = tid; i < (256 + 2 * BN) * 4; i += 256) {
            int row = i >> 2, seg = (i & 3) << 3;
            const bf16* src; uint32_t toff; int r;
            if (row < 256) {
                r = row & 127;
                src  = (row < 128 ? Ah : Al) + (long)(bm + r) * lda + kt + seg;
                toff = (row < 128) ? 0u : (uint32_t)AST;
            } else {
                int rb = row - 256;
                r = rb & (BN - 1);
                src  = (rb < BN ? Bh : Bl) + (long)(bn + r) * ldb + kt + seg;
                toff = (rb < BN) ? (uint32_t)(2 * AST) : (uint32_t)(2 * AST + BST);
            }
            uint32_t dst = sb + (toff + (uint32_t)(r * KS + seg)) * 2u;
            CPA16(dst, src);
        }
        CPA_COMMIT();
    };

    const int NC = K >> 5;
    load_stage(0, 0);

    for (int c = 0; c < NC; c++) {
        int s = c & 1;
        if (c + 1 < NC) { load_stage(s ^ 1, (c + 1) << 5); CPA_WAIT1(); }
        else            { CPA_WAIT0(); }
        __syncthreads();

        const bf16* sAh = sm + s * STG;
        const bf16* sAl = sAh + AST;
        const bf16* sBh = sAh + 2 * AST;
        const bf16* sBl = sBh + BST;

#pragma unroll
        for (int ks = 0; ks < 2; ks++) {
            int k0 = ks * 16;
            unsigned aH[2][4], aL[2][4];
#pragma unroll
            for (int mt = 0; mt < 2; mt++) {
                int o = (mb + mt * 16 + lr) * KS + k0 + lc;
                aH[mt][0] = *(const unsigned*)&sAh[o];
                aH[mt][1] = *(const unsigned*)&sAh[o + 8 * KS];
                aH[mt][2] = *(const unsigned*)&sAh[o + 8];
                aH[mt][3] = *(const unsigned*)&sAh[o + 8 * KS + 8];
                aL[mt][0] = *(const unsigned*)&sAl[o];
                aL[mt][1] = *(const unsigned*)&sAl[o + 8 * KS];
                aL[mt][2] = *(const unsigned*)&sAl[o + 8];
                aL[mt][3] = *(const unsigned*)&sAl[o + 8 * KS + 8];
            }
#pragma unroll
            for (int nc = 0; nc < NT; nc += 4) {
                unsigned bH[4][2], bL[4][2];
#pragma unroll
                for (int j = 0; j < 4; j++) {
                    int o = (nb + (nc + j) * 8 + lr) * KS + k0 + lc;
                    bH[j][0] = *(const unsigned*)&sBh[o];
                    bH[j][1] = *(const unsigned*)&sBh[o + 8];
                    bL[j][0] = *(const unsigned*)&sBl[o];
                    bL[j][1] = *(const unsigned*)&sBl[o + 8];
                }
#pragma unroll
                for (int mt = 0; mt < 2; mt++)
#pragma unroll
                    for (int j = 0; j < 4; j++) {
                        mma16816(acc[mt][nc + j], aH[mt], bH[j]);
                        mma16816(acc[mt][nc + j], aH[mt], bL[j]);
                        mma16816(acc[mt][nc + j], aL[mt], bH[j]);
                    }
            }
        }
        __syncthreads();
    }

#pragma unroll
    for (int mt = 0; mt < 2; mt++) {
#pragma unroll
        for (int nt = 0; nt < NT; nt++) {
            int gm = bm + mb + mt * 16 + lr;
            int gn = bn + nb + nt * 8 + lc;
            float v0 = acc[mt][nt][0] * alpha;
            float v1 = acc[mt][nt][1] * alpha;
            float v2 = acc[mt][nt][2] * alpha;
            float v3 = acc[mt][nt][3] * alpha;
            if (bias) {
                float b0 = bias[gn], b1 = bias[gn + 1];
                v0 += b0; v1 += b1; v2 += b0; v3 += b1;
            }
            if (relu) {
                v0 = fmaxf(v0, 0.f); v1 = fmaxf(v1, 0.f);
                v2 = fmaxf(v2, 0.f); v3 = fmaxf(v3, 0.f);
            }
            long o0 = cbase + (long)gm * ldc + gn;
            long o1 = cbase + (long)(gm + 8) * ldc + gn;
            if (mode == 0) {
                float2 r0; r0.x = v0; r0.y = v1;
                float2 r1; r1.x = v2; r1.y = v3;
                *(float2*)(Cf + o0) = r0;
                *(float2*)(Cf + o1) = r1;
            } else {
                bf16 h0, l0, h1, l1;
                split2(v0, h0, l0); split2(v1, h1, l1);
                *(bf162*)(Chi + o0) = __halves2bfloat162(h0, h1);
                *(bf162*)(Clo + o0) = __halves2bfloat162(l0, l1);
                split2(v2, h0, l0); split2(v3, h1, l1);
                *(bf162*)(Chi + o1) = __halves2bfloat162(h0, h1);
                *(bf162*)(Clo + o1) = __halves2bfloat162(l0, l1);
            }
        }
    }
}

// ---------------- fused flash attention --------------------------------------
// Per CTA: (b,h) pair, 128 q-rows. Iterates 4 key-tiles of 128.
// Warp layout: wm = wid&3 -> 32 q-rows; wn = wid>>2 -> 64-key column half.
// S = Q@K^T (bf16x3), online softmax in regs, P@V^T (bf16x3) into ctx partials.
__global__ void __launch_bounds__(256) flash_attn(
    const bf16* __restrict__ Qhi_g, const bf16* __restrict__ Qlo_g,
    const bf16* __restrict__ Khi_g, const bf16* __restrict__ Klo_g,
    const bf16* __restrict__ VThi_g, const bf16* __restrict__ VTlo_g,
    bf16* __restrict__ Chi, bf16* __restrict__ Clo)
{
    constexpr int KSF = 72;    // Q/K smem row stride (64 data + 8 pad)
    constexpr int VSF = 136;   // VT smem row stride (128 data + 8 pad)
    extern __shared__ bf16 sm[];
    bf16* sQh = sm;                    // 128*72
    bf16* sQl = sQh + 128*KSF;
    bf16* sKh = sQl + 128*KSF;
    bf16* sKl = sKh + 128*KSF;
    bf16* sVh = sKl + 128*KSF;         // 64*136
    bf16* sVl = sVh + 64*VSF;
    float* sred = (float*)(sVl + 64*VSF);   // 256 floats
    float* sctx = (float*)sKh;              // overlay on K region (>=34816B)

    uint32_t uQh = smem_u32(sQh), uQl = smem_u32(sQl);
    uint32_t uKh = smem_u32(sKh), uKl = smem_u32(sKl);
    uint32_t uVh = smem_u32(sVh), uVl = smem_u32(sVl);

    int tid = threadIdx.x, wid = tid >> 5, lane = tid & 31;
    int wm = wid & 3, wn = wid >> 2;
    int mb = wm * 32;
    int lr = lane >> 2, lc = (lane & 3) * 2;

    int qb = blockIdx.x * 128;
    int bb = blockIdx.y / HNUM, hh = blockIdx.y % HNUM;
    const bf16* Qh = Qhi_g + (long)(bb*SAQ + qb) * EDIM + hh*DHEAD;
    const bf16* Ql = Qlo_g + (long)(bb*SAQ + qb) * EDIM + hh*DHEAD;
    const bf16* Kh = Khi_g + (long)(bb*SBK) * EDIM + hh*DHEAD;
    const bf16* Kl = Klo_g + (long)(bb*SBK) * EDIM + hh*DHEAD;
    const bf16* Vh = VThi_g + (long)(hh*DHEAD) * MROWS + bb*SBK;
    const bf16* Vl = VTlo_g + (long)(hh*DHEAD) * MROWS + bb*SBK;

    // load Q tile once (hi+lo): 128 rows x 8 x 16B
    for (int i = tid; i < 128*8; i += 256) {
        int r = i >> 3, seg = (i & 7) << 3;
        uint32_t d = (uint32_t)((r * KSF + seg) * 2);
        CPA16(uQh + d, Qh + (long)r * EDIM + seg);
        CPA16(uQl + d, Ql + (long)r * EDIM + seg);
    }
    CPA_COMMIT();

    float mrun[4], lrun[4];
#pragma unroll
    for (int i = 0; i < 4; i++) { mrun[i] = -1e30f; lrun[i] = 0.f; }
    float cacc[2][8][4];
#pragma unroll
    for (int mt = 0; mt < 2; mt++)
#pragma unroll
        for (int nd = 0; nd < 8; nd++)
#pragma unroll
            for (int q = 0; q < 4; q++) cacc[mt][nd][q] = 0.f;

    for (int kt = 0; kt < 4; kt++) {
        __syncthreads();     // guard smem (K/V and sred) reuse
        // load K tile: 128 keys x 64 d
        for (int i = tid; i < 128*8; i += 256) {
            int r = i >> 3, seg = (i & 7) << 3;
            uint32_t d = (uint32_t)((r * KSF + seg) * 2);
            long go = (long)(kt*128 + r) * EDIM + seg;
            CPA16(uKh + d, Kh + go);
            CPA16(uKl + d, Kl + go);
        }
        // load VT tile: 64 d x 128 keys
        for (int i = tid; i < 64*16; i += 256) {
            int r = i >> 4, seg = (i & 15) << 3;
            uint32_t d = (uint32_t)((r * VSF + seg) * 2);
            long go = (long)r * MROWS + kt*128 + seg;
            CPA16(uVh + d, Vh + go);
            CPA16(uVl + d, Vl + go);
        }
        CPA_COMMIT(); CPA_WAIT0();
        __syncthreads();

        // ---- S = Q @ K^T over k=64 ----
        float sacc[2][8][4];
#pragma unroll
        for (int mt = 0; mt < 2; mt++)
#pragma unroll
            for (int nt = 0; nt < 8; nt++)
#pragma unroll
                for (int q = 0; q < 4; q++) sacc[mt][nt][q] = 0.f;

#pragma unroll
        for (int k0 = 0; k0 < 64; k0 += 16) {
            unsigned aH[2][4], aL[2][4];
#pragma unroll
            for (int mt = 0; mt < 2; mt++) {
                int o = (mb + mt*16 + lr) * KSF + k0 + lc;
                aH[mt][0] = *(const unsigned*)&sQh[o];
                aH[mt][1] = *(const unsigned*)&sQh[o + 8*KSF];
                aH[mt][2] = *(const unsigned*)&sQh[o + 8];
                aH[mt][3] = *(const unsigned*)&sQh[o + 8*KSF + 8];
                aL[mt][0] = *(const unsigned*)&sQl[o];
                aL[mt][1] = *(const unsigned*)&sQl[o + 8*KSF];
                aL[mt][2] = *(const unsigned*)&sQl[o + 8];
                aL[mt][3] = *(const unsigned*)&sQl[o + 8*KSF + 8];
            }
#pragma unroll
            for (int nt = 0; nt < 8; nt++) {
                int o = (wn*64 + nt*8 + lr) * KSF + k0 + lc;
                unsigned bH[2], bL[2];
                bH[0] = *(const unsigned*)&sKh[o];
                bH[1] = *(const unsigned*)&sKh[o + 8];
                bL[0] = *(const unsigned*)&sKl[o];
                bL[1] = *(const unsigned*)&sKl[o + 8];
#pragma unroll
                for (int mt = 0; mt < 2; mt++) {
                    mma16816(sacc[mt][nt], aH[mt], bH);
                    mma16816(sacc[mt][nt], aH[mt], bL);
                    mma16816(sacc[mt][nt], aL[mt], bH);
                }
            }
        }

        // ---- row max (scaled), cross-warp via smem ----
#pragma unroll
        for (int mt = 0; mt < 2; mt++)
#pragma unroll
            for (int h = 0; h < 2; h++) {
                float mx = -1e30f;
#pragma unroll
                for (int nt = 0; nt < 8; nt++)
                    mx = fmaxf(mx, fmaxf(sacc[mt][nt][h*2], sacc[mt][nt][h*2+1]));
                mx *= 0.125f;
                mx = fmaxf(mx, __shfl_xor_sync(0xffffffffu, mx, 1));
                mx = fmaxf(mx, __shfl_xor_sync(0xffffffffu, mx, 2));
                if ((lane & 3) == 0)
                    sred[wn*128 + mb + mt*16 + h*8 + lr] = mx;
            }
        __syncthreads();
        float mnew[4], alpha[4];
#pragma unroll
        for (int mt = 0; mt < 2; mt++)
#pragma unroll
            for (int h = 0; h < 2; h++) {
                int idx = mt*2 + h;
                int row = mb + mt*16 + h*8 + lr;
                float tm = fmaxf(sred[row], sred[128 + row]);
                float mn = fmaxf(mrun[idx], tm);
                alpha[idx] = expf(mrun[idx] - mn);
                mnew[idx] = mn; mrun[idx] = mn;
            }

        // ---- exp, l update, rescale ctx ----
#pragma unroll
        for (int mt = 0; mt < 2; mt++)
#pragma unroll
            for (int h = 0; h < 2; h++) {
                int idx = mt*2 + h;
                float ls = 0.f;
#pragma unroll
                for (int nt = 0; nt < 8; nt++) {
                    float p0 = expf(sacc[mt][nt][h*2]   * 0.125f - mnew[idx]);
                    float p1 = expf(sacc[mt][nt][h*2+1] * 0.125f - mnew[idx]);
                    sacc[mt][nt][h*2]   = p0;
                    sacc[mt][nt][h*2+1] = p1;
                    ls += p0 + p1;
                }
                lrun[idx] = lrun[idx] * alpha[idx] + ls;
            }
#pragma unroll
        for (int mt = 0; mt < 2; mt++)
#pragma unroll
            for (int nd = 0; nd < 8; nd++) {
                cacc[mt][nd][0] *= alpha[mt*2];
                cacc[mt][nd][1] *= alpha[mt*2];
                cacc[mt][nd][2] *= alpha[mt*2+1];
                cacc[mt][nd][3] *= alpha[mt*2+1];
            }

        // ---- ctx += P @ V^T over warp's 64 keys ----
#pragma unroll
        for (int kk = 0; kk < 4; kk++) {
            unsigned aH[2][4], aL[2][4];
#pragma unroll
            for (int mt = 0; mt < 2; mt++) {
                pack_hl(sacc[mt][2*kk][0],   sacc[mt][2*kk][1],   aH[mt][0], aL[mt][0]);
                pack_hl(sacc[mt][2*kk][2],   sacc[mt][2*kk][3],   aH[mt][1], aL[mt][1]);
                pack_hl(sacc[mt][2*kk+1][0], sacc[mt][2*kk+1][1], aH[mt][2], aL[mt][2]);
                pack_hl(sacc[mt][2*kk+1][2], sacc[mt][2*kk+1][3], aH[mt][3], aL[mt][3]);
            }
#pragma unroll
            for (int nd = 0; nd < 8; nd++) {
                int o = (nd*8 + lr) * VSF + wn*64 + kk*16 + lc;
                unsigned bH[2], bL[2];
                bH[0] = *(const unsigned*)&sVh[o];
                bH[1] = *(const unsigned*)&sVh[o + 8];
                bL[0] = *(const unsigned*)&sVl[o];
                bL[1] = *(const unsigned*)&sVl[o + 8];
#pragma unroll
                for (int mt = 0; mt < 2; mt++) {
                    mma16816(cacc[mt][nd], aH[mt], bH);
                    mma16816(cacc[mt][nd], aH[mt], bL);
                    mma16816(cacc[mt][nd], aL[mt], bH);
                }
            }
        }
    }

    // ---- finalize: l totals, combine wn halves, normalize, store -----------
#pragma unroll
    for (int mt = 0; mt < 2; mt++)
#pragma unroll
        for (int h = 0; h < 2; h++) {
            int idx = mt*2 + h;
            float ls = lrun[idx];
            ls += __shfl_xor_sync(0xffffffffu, ls, 1);
            ls += __shfl_xor_sync(0xffffffffu, ls, 2);
            if ((lane & 3) == 0)
                sred[wn*128 + mb + mt*16 + h*8 + lr] = ls;
        }
    __syncthreads();
    float lt[4];
#pragma unroll
    for (int mt = 0; mt < 2; mt++)
#pragma unroll
        for (int h = 0; h < 2; h++) {
            int row = mb + mt*16 + h*8 + lr;
            lt[mt*2 + h] = sred[row] + sred[128 + row];
        }
    __syncthreads();   // all reads of K/V smem + sred done before sctx overlay

    if (wn == 0) {
#pragma unroll
        for (int mt = 0; mt < 2; mt++)
#pragma unroll
            for (int nd = 0; nd < 8; nd++) {
                int r0 = mb + mt*16 + lr;
                sctx[r0*68 + nd*8 + lc]       = cacc[mt][nd][0];
                sctx[r0*68 + nd*8 + lc + 1]   = cacc[mt][nd][1];
                sctx[(r0+8)*68 + nd*8 + lc]     = cacc[mt][nd][2];
                sctx[(r0+8)*68 + nd*8 + lc + 1] = cacc[mt][nd][3];
            }
    }
    __syncthreads();
    if (wn == 1) {
        long gbase = (long)(bb*SAQ + qb) * EDIM + hh*DHEAD;
#pragma unroll
        for (int mt = 0; mt < 2; mt++)
#pragma unroll
            for (int nd = 0; nd < 8; nd++) {
                int r0 = mb + mt*16 + lr;
                float inv0 = 1.f / lt[mt*2];
                float inv1 = 1.f / lt[mt*2+1];
                float v0 = (sctx[r0*68 + nd*8 + lc]     + cacc[mt][nd][0]) * inv0;
                float v1 = (sctx[r0*68 + nd*8 + lc + 1] + cacc[mt][nd][1]) * inv0;
                float v2 = (sctx[(r0+8)*68 + nd*8 + lc]     + cacc[mt][nd][2]) * inv1;
                float v3 = (sctx[(r0+8)*68 + nd*8 + lc + 1] + cacc[mt][nd][3]) * inv1;
                bf16 h0, l0, h1, l1;
                long o0 = gbase + (long)r0 * EDIM + nd*8 + lc;
                long o1 = gbase + (long)(r0+8) * EDIM + nd*8 + lc;
                split2(v0, h0, l0); split2(v1, h1, l1);
                *(bf162*)(Chi + o0) = __halves2bfloat162(h0, h1);
                *(bf162*)(Clo + o0) = __halves2bfloat162(l0, l1);
                split2(v2, h0, l0); split2(v3, h1, l1);
                *(bf162*)(Chi + o1) = __halves2bfloat162(h0, h1);
                *(bf162*)(Clo + o1) = __halves2bfloat162(l0, l1);
            }
    }
}

// ---------------- fused residual + LayerNorm (+ split outputs) --------------
__global__ void add_ln(const float* __restrict__ X, const float* __restrict__ R,
                       const float* __restrict__ g, const float* __restrict__ b,
                       float* __restrict__ Y, bf16* __restrict__ Yhi, bf16* __restrict__ Ylo)
{
    long row = blockIdx.x;
    const float* x = X + row * EDIM;
    const float* r = R + row * EDIM;
    int t = threadIdx.x;
    float v[4];
#pragma unroll
    for (int i = 0; i < 4; i++) v[i] = x[t + i*256] + r[t + i*256];
    __shared__ float red[256];
    red[t] = v[0] + v[1] + v[2] + v[3]; __syncthreads();
    for (int s = 128; s > 0; s >>= 1) { if (t < s) red[t] += red[t+s]; __syncthreads(); }
    float mean = red[0] * (1.f / EDIM); __syncthreads();
    float q = 0.f;
#pragma unroll
    for (int i = 0; i < 4; i++) { float d = v[i] - mean; q = fmaf(d, d, q); }
    red[t] = q; __syncthreads();
    for (int s = 128; s > 0; s >>= 1) { if (t < s) red[t] += red[t+s]; __syncthreads(); }
    float inv = rsqrtf(red[0] * (1.f / EDIM) + 1e-5f);
#pragma unroll
    for (int i = 0; i < 4; i++) {
        int c = t + i*256;
        float y = (v[i] - mean) * inv * g[c] + b[c];
        Y[row * EDIM + c] = y;
        bf16 h, l; split2(y, h, l);
        Yhi[row * EDIM + c] = h;
        Ylo[row * EDIM + c] = l;
    }
}

// ---------------- classifier + loss ------------------------------------------
__global__ void classify(const float* __restrict__ Aout, const float* __restrict__ cw,
                         const float* __restrict__ cb, const int* __restrict__ labels,
                         const int* __restrict__ maskA, const int* __restrict__ cand,
                         float* __restrict__ outp, float* __restrict__ part)
{
    int warp = threadIdx.x >> 5, lane = threadIdx.x & 31;
    int row = blockIdx.x * 8 + warp;
    const float* a = Aout + (long)row * EDIM;
    float d0 = 0.f, d1 = 0.f;
    for (int e = lane; e < EDIM; e += 32) {
        float av = a[e];
        d0 = fmaf(av, cw[e], d0);
        d1 = fmaf(av, cw[EDIM + e], d1);
    }
#pragma unroll
    for (int o = 16; o > 0; o >>= 1) {
        d0 += __shfl_down_sync(0xffffffffu, d0, o);
        d1 += __shfl_down_sync(0xffffffffu, d1, o);
    }
    __shared__ float pw[8][2];
    if (lane == 0) {
        float e0 = d0 + cb[0], e1 = d1 + cb[1];
        int lb = labels[row];
        float mx = fmaxf(e0, e1);
        float lse = mx + logf(expf(e0 - mx) + expf(e1 - mx));
        float ce = lse - ((lb == 1) ? e1 : e0);
        float w = (lb == 1) ? 5.0f : 1.0f;
        float valid = (maskA[row] == 1) ? 1.0f : 0.0f;
        pw[warp][0] = ce * w * valid;
        pw[warp][1] = valid;
        int pred1 = (e1 > e0) ? 1 : 0;
        outp[1 + row] = ((cand[row] == 1) && pred1) ? 1.0f : 0.0f;
    }
    __syncthreads();
    if (threadIdx.x == 0) {
        float s0 = 0.f, s1 = 0.f;
#pragma unroll
        for (int i = 0; i < 8; i++) { s0 += pw[i][0]; s1 += pw[i][1]; }
        part[blockIdx.x * 2 + 0] = s0;
        part[blockIdx.x * 2 + 1] = s1;
    }
}

__global__ void finalize(const float* __restrict__ part, float* __restrict__ outp) {
    __shared__ float r0[512], r1[512];
    int t = threadIdx.x;
    r0[t] = part[t * 2 + 0];
    r1[t] = part[t * 2 + 1];
    __syncthreads();
    for (int s = 256; s > 0; s >>= 1) {
        if (t < s) { r0[t] += r0[t+s]; r1[t] += r1[t+s]; }
        __syncthreads();
    }
    if (t == 0) outp[0] = r0[0] / fmaxf(r1[0], 1.0f);
}

// ---------------- host orchestration ----------------------------------------
extern "C" void kernel_launch(void* const* d_in, const int* in_sizes, int n_in,
                              void* d_out, int out_size)
{
    const float* enc   = (const float*)d_in[0];
    const float* dsc   = (const float*)d_in[1];
    const int*   maskA = (const int*)  d_in[2];
    const int*   cand  = (const int*)  d_in[3];
    const int*   labels= (const int*)  d_in[4];
    const float* ipw   = (const float*)d_in[5];
    const float* ipb   = (const float*)d_in[6];
    const float* ow    = (const float*)d_in[7];
    const float* ob    = (const float*)d_in[8];
    const float* g1    = (const float*)d_in[9];
    const float* b1    = (const float*)d_in[10];
    const float* W1    = (const float*)d_in[11];
    const float* bb1   = (const float*)d_in[12];
    const float* W2    = (const float*)d_in[13];
    const float* bb2   = (const float*)d_in[14];
    const float* g2    = (const float*)d_in[15];
    const float* b2    = (const float*)d_in[16];
    const float* cw    = (const float*)d_in[17];
    const float* cb    = (const float*)d_in[18];

    float *A, *A1, *TMP, *V, *PART;
    bf16 *Ahi,*Alo,*A1hi,*A1lo,*Dhi,*Dlo,*Qhi,*Qlo,*Khi,*Klo,*VThi,*VTlo;
    bf16 *CThi,*CTlo,*MIDhi,*MIDlo;
    bf16 *IPWhi,*IPWlo,*OWhi,*OWlo,*W1hi,*W1lo,*W2hi,*W2lo;
    cudaGetSymbolAddress((void**)&A, g_A);     cudaGetSymbolAddress((void**)&A1, g_A1);
    cudaGetSymbolAddress((void**)&TMP, g_TMP); cudaGetSymbolAddress((void**)&V, g_V);
    cudaGetSymbolAddress((void**)&PART, g_PART);
    cudaGetSymbolAddress((void**)&Ahi, g_Ahi); cudaGetSymbolAddress((void**)&Alo, g_Alo);
    cudaGetSymbolAddress((void**)&A1hi, g_A1hi); cudaGetSymbolAddress((void**)&A1lo, g_A1lo);
    cudaGetSymbolAddress((void**)&Dhi, g_Dhi); cudaGetSymbolAddress((void**)&Dlo, g_Dlo);
    cudaGetSymbolAddress((void**)&Qhi, g_Qhi); cudaGetSymbolAddress((void**)&Qlo, g_Qlo);
    cudaGetSymbolAddress((void**)&Khi, g_Khi); cudaGetSymbolAddress((void**)&Klo, g_Klo);
    cudaGetSymbolAddress((void**)&VThi, g_VThi); cudaGetSymbolAddress((void**)&VTlo, g_VTlo);
    cudaGetSymbolAddress((void**)&CThi, g_CThi); cudaGetSymbolAddress((void**)&CTlo, g_CTlo);
    cudaGetSymbolAddress((void**)&MIDhi, g_MIDhi); cudaGetSymbolAddress((void**)&MIDlo, g_MIDlo);
    cudaGetSymbolAddress((void**)&IPWhi, g_IPWhi); cudaGetSymbolAddress((void**)&IPWlo, g_IPWlo);
    cudaGetSymbolAddress((void**)&OWhi, g_OWhi); cudaGetSymbolAddress((void**)&OWlo, g_OWlo);
    cudaGetSymbolAddress((void**)&W1hi, g_W1hi); cudaGetSymbolAddress((void**)&W1lo, g_W1lo);
    cudaGetSymbolAddress((void**)&W2hi, g_W2hi); cudaGetSymbolAddress((void**)&W2lo, g_W2lo);

    const int SMEM128 = 2 * (2*128*40 + 2*128*40) * 2;   // 81920 B
    const int SMEM_FA = (4*128*72 + 2*64*136) * 2 + 256*4;  // 109568 B
    static int attr_done = 0;
    if (!attr_done) {
        cudaFuncSetAttribute(gemm_bf3<128>, cudaFuncAttributeMaxDynamicSharedMemorySize, SMEM128);
        cudaFuncSetAttribute(flash_attn, cudaFuncAttributeMaxDynamicSharedMemorySize, SMEM_FA);
        attr_done = 1;
    }

    // ---- per-call splits ----
    int nIPW = LNUM*3*EDIM*EDIM, nOW = LNUM*EDIM*EDIM;
    int nW1 = LNUM*FDIM*EDIM,    nW2 = LNUM*EDIM*FDIM;
    split_f<<<(nIPW+255)/256, 256>>>(ipw, IPWhi, IPWlo, nIPW);
    split_f<<<(nOW +255)/256, 256>>>(ow,  OWhi,  OWlo,  nOW);
    split_f<<<(nW1 +255)/256, 256>>>(W1,  W1hi,  W1lo,  nW1);
    split_f<<<(nW2 +255)/256, 256>>>(W2,  W2hi,  W2lo,  nW2);
    split_f<<<(BDIM*SBK*EDIM+255)/256, 256>>>(dsc, Dhi, Dlo, BDIM*SBK*EDIM);
    split_f<<<(MROWS*EDIM+255)/256, 256>>>(enc, Ahi, Alo, MROWS*EDIM);
    copy_f <<<(MROWS*EDIM+255)/256, 256>>>(enc, A, MROWS*EDIM);

    dim3 gP (EDIM/128, MROWS/128, 1);
    dim3 gF1(FDIM/128, MROWS/128, 1);
    dim3 gFA(SAQ/128, BDIM*HNUM, 1);
    dim3 gT (EDIM/32, MROWS/32, 1);
    dim3 bT (32, 8, 1);

    for (int l = 0; l < LNUM; l++) {
        const bf16 *wqh = IPWhi + (long)l*3*EDIM*EDIM, *wql = IPWlo + (long)l*3*EDIM*EDIM;
        const bf16 *wkh = wqh + EDIM*EDIM, *wkl = wql + EDIM*EDIM;
        const bf16 *wvh = wkh + EDIM*EDIM, *wvl = wkl + EDIM*EDIM;
        const float *bq = ipb + (long)l*3*EDIM, *bk = bq + EDIM, *bv = bk + EDIM;

        gemm_bf3<128><<<gP, 256, SMEM128>>>(Ahi, Alo, wqh, wql, bq, 0, Qhi, Qlo,
            EDIM, EDIM, EDIM, EDIM, 0,0,0,0,0,0,1, 1.0f, 1, 0);
        gemm_bf3<128><<<gP, 256, SMEM128>>>(Dhi, Dlo, wkh, wkl, bk, 0, Khi, Klo,
            EDIM, EDIM, EDIM, EDIM, 0,0,0,0,0,0,1, 1.0f, 1, 0);
        gemm_bf3<128><<<gP, 256, SMEM128>>>(Dhi, Dlo, wvh, wvl, bv, V, 0, 0,
            EDIM, EDIM, EDIM, EDIM, 0,0,0,0,0,0,1, 1.0f, 0, 0);
        transpose_split<<<gT, bT>>>(V, VThi, VTlo);

        // fused attention: scores + softmax + P@V -> split ctx
        flash_attn<<<gFA, 256, SMEM_FA>>>(Qhi, Qlo, Khi, Klo, VThi, VTlo, CThi, CTlo);

        gemm_bf3<128><<<gP, 256, SMEM128>>>(CThi, CTlo, OWhi + (long)l*EDIM*EDIM,
            OWlo + (long)l*EDIM*EDIM, ob + (long)l*EDIM, TMP, 0, 0,
            EDIM, EDIM, EDIM, EDIM, 0,0,0,0,0,0,1, 1.0f, 0, 0);

        add_ln<<<MROWS, 256>>>(A, TMP, g1 + (long)l*EDIM, b1 + (long)l*EDIM,
                               A1, A1hi, A1lo);

        gemm_bf3<128><<<gF1, 256, SMEM128>>>(A1hi, A1lo, W1hi + (long)l*FDIM*EDIM,
            W1lo + (long)l*FDIM*EDIM, bb1 + (long)l*FDIM, 0, MIDhi, MIDlo,
            EDIM, EDIM, EDIM, FDIM, 0,0,0,0,0,0,1, 1.0f, 1, 1);

        gemm_bf3<128><<<gP, 256, SMEM128>>>(MIDhi, MIDlo, W2hi + (long)l*EDIM*FDIM,
            W2lo + (long)l*EDIM*FDIM, bb2 + (long)l*EDIM, TMP, 0, 0,
            FDIM, FDIM, FDIM, EDIM, 0,0,0,0,0,0,1, 1.0f, 0, 0);

        add_ln<<<MROWS, 256>>>(A1, TMP, g2 + (long)l*EDIM, b2 + (long)l*EDIM,
                               A, Ahi, Alo);
    }

    classify<<<MROWS/8, 256>>>(A, cw, cb, labels, maskA, cand, (float*)d_out, PART);
    finalize<<<1, 512>>>(PART, (float*)d_out);
}

// round 6
// speedup vs baseline: 1.4474x; 1.4474x over previous
#include <cuda_runtime.h>
#include <cuda_bf16.h>
#include <math.h>
#include <stdint.h>

// Problem dims
#define LNUM 9
#define BDIM 8
#define SAQ 512
#define SBK 512
#define EDIM 1024
#define HNUM 16
#define DHEAD 64
#define FDIM 4096
#define MROWS (BDIM*SAQ)          // 4096

typedef __nv_bfloat16 bf16;
typedef __nv_bfloat162 bf162;

// ---------------- scratch (device globals) ----------------------------------
__device__ float g_A  [MROWS*EDIM];
__device__ float g_A1 [MROWS*EDIM];
__device__ float g_TMP[MROWS*EDIM];
__device__ float g_V  [MROWS*EDIM];
__device__ float g_S  [(long)BDIM*HNUM*SAQ*SBK];
__device__ float g_PART[1024];

__device__ bf16 g_Ahi [MROWS*EDIM],  g_Alo [MROWS*EDIM];
__device__ bf16 g_A1hi[MROWS*EDIM],  g_A1lo[MROWS*EDIM];
__device__ bf16 g_Dhi [BDIM*SBK*EDIM], g_Dlo [BDIM*SBK*EDIM];
__device__ bf16 g_Qhi [MROWS*EDIM],  g_Qlo [MROWS*EDIM];
__device__ bf16 g_Khi [MROWS*EDIM],  g_Klo [MROWS*EDIM];
__device__ bf16 g_VThi[EDIM*MROWS],  g_VTlo[EDIM*MROWS];
__device__ bf16 g_Phi [(long)BDIM*HNUM*SAQ*SBK], g_Plo[(long)BDIM*HNUM*SAQ*SBK];
__device__ bf16 g_CThi[MROWS*EDIM],  g_CTlo[MROWS*EDIM];
__device__ bf16 g_MIDhi[(long)MROWS*FDIM], g_MIDlo[(long)MROWS*FDIM];
__device__ bf16 g_IPWhi[LNUM*3*EDIM*EDIM], g_IPWlo[LNUM*3*EDIM*EDIM];
__device__ bf16 g_OWhi [LNUM*EDIM*EDIM],   g_OWlo [LNUM*EDIM*EDIM];
__device__ bf16 g_W1hi [(long)LNUM*FDIM*EDIM], g_W1lo[(long)LNUM*FDIM*EDIM];
__device__ bf16 g_W2hi [(long)LNUM*EDIM*FDIM], g_W2lo[(long)LNUM*EDIM*FDIM];

// ---------------- helpers ----------------------------------------------------
__device__ __forceinline__ void split2(float v, bf16& h, bf16& l) {
    h = __float2bfloat16(v);
    l = __float2bfloat16(v - __bfloat162float(h));
}

__device__ __forceinline__ uint32_t smem_u32(const void* p) {
    uint32_t a;
    asm("{ .reg .u64 t; cvta.to.shared.u64 t, %1; cvt.u32.u64 %0, t; }"
        : "=r"(a) : "l"(p));
    return a;
}

#define CPA16(dst, src) \
    asm volatile("cp.async.cg.shared.global [%0], [%1], 16;" :: "r"(dst), "l"(src))
#define CPA_COMMIT() asm volatile("cp.async.commit_group;" ::: "memory")
#define CPA_WAIT1()  asm volatile("cp.async.wait_group 1;" ::: "memory")
#define CPA_WAIT0()  asm volatile("cp.async.wait_group 0;" ::: "memory")

__device__ __forceinline__ void ldsm4(unsigned* r, uint32_t addr) {
    asm volatile("ldmatrix.sync.aligned.m8n8.x4.shared.b16 {%0,%1,%2,%3}, [%4];"
        : "=r"(r[0]), "=r"(r[1]), "=r"(r[2]), "=r"(r[3]) : "r"(addr));
}

__global__ void copy_f(const float* __restrict__ src, float* __restrict__ dst, int n) {
    int i = blockIdx.x * blockDim.x + threadIdx.x;
    if (i < n) dst[i] = src[i];
}

__global__ void split_f(const float* __restrict__ src, bf16* __restrict__ hi,
                        bf16* __restrict__ lo, int n) {
    int i = blockIdx.x * blockDim.x + threadIdx.x;
    if (i < n) { bf16 h, l; split2(src[i], h, l); hi[i] = h; lo[i] = l; }
}

// V [4096][1024] f32 -> VT [1024][4096] split bf16
__global__ void transpose_split(const float* __restrict__ V,
                                bf16* __restrict__ VThi, bf16* __restrict__ VTlo) {
    __shared__ float t[32][33];
    int bx = blockIdx.x * 32, by = blockIdx.y * 32;
    int tx = threadIdx.x, ty = threadIdx.y;
#pragma unroll
    for (int i = 0; i < 4; i++)
        t[ty + i*8][tx] = V[(long)(by + ty + i*8) * EDIM + bx + tx];
    __syncthreads();
#pragma unroll
    for (int i = 0; i < 4; i++) {
        float v = t[tx][ty + i*8];
        bf16 h, l; split2(v, h, l);
        long o = (long)(bx + ty + i*8) * MROWS + by + tx;
        VThi[o] = h; VTlo[o] = l;
    }
}

__device__ __forceinline__ void mma16816(float* d, const unsigned* a, const unsigned* b) {
    asm volatile(
        "mma.sync.aligned.m16n8k16.row.col.f32.bf16.bf16.f32 "
        "{%0,%1,%2,%3},{%4,%5,%6,%7},{%8,%9},{%0,%1,%2,%3};"
        : "+f"(d[0]), "+f"(d[1]), "+f"(d[2]), "+f"(d[3])
        : "r"(a[0]), "r"(a[1]), "r"(a[2]), "r"(a[3]), "r"(b[0]), "r"(b[1]));
}

// ---------------- bf16x3 warp-MMA GEMM (TN), cp.async + ldmatrix -------------
// C[m,n] = alpha * sum_k (Ahi+Alo)[m,k] * (Bhi+Blo)[n,k]  (+bias, relu)
// dropping the Alo*Blo term. BM=128, BK=32, BN template (128 or 64).
// mode 0: store fp32 to Cf.   mode 1: split-store bf16 to Chi/Clo.
template<int BN>
__global__ void __launch_bounds__(256, 2) gemm_bf3(
    const bf16* __restrict__ Ahi_g, const bf16* __restrict__ Alo_g,
    const bf16* __restrict__ Bhi_g, const bf16* __restrict__ Blo_g,
    const float* __restrict__ bias,
    float* __restrict__ Cf, bf16* __restrict__ Chi, bf16* __restrict__ Clo,
    int K, int lda, int ldb, int ldc,
    long sAb, long sAh, long sBb, long sBh, long sCb, long sCh, int nH,
    float alpha, int mode, int relu)
{
    constexpr int KS  = 40;               // padded smem row stride (80B = 5*16B)
    constexpr int AST = 128 * KS;
    constexpr int BST = BN * KS;
    constexpr int STG = 2 * AST + 2 * BST;
    constexpr int NT  = BN / 16;          // 8-wide n tiles per warp (pairs)

    extern __shared__ bf16 sm[];
    uint32_t smb = smem_u32(sm);

    int bz = blockIdx.z;
    int bb = bz / nH, hh = bz % nH;
    const bf16* Ah = Ahi_g + bb * sAb + hh * sAh;
    const bf16* Al = Alo_g + bb * sAb + hh * sAh;
    const bf16* Bh = Bhi_g + bb * sBb + hh * sBh;
    const bf16* Bl = Blo_g + bb * sBb + hh * sBh;
    long cbase = bb * sCb + hh * sCh;

    int bm = blockIdx.y * 128, bn = blockIdx.x * BN;
    int tid = threadIdx.x;
    int wid = tid >> 5, lane = tid & 31;
    int wm = wid & 3, wn = wid >> 2;
    int mb = wm * 32, nb = wn * (BN / 2);
    int lr = lane >> 2, lc = (lane & 3) * 2;

    // ldmatrix per-lane offsets
    int a_ro = lane & 15;                          // m-row within 16
    int a_co = (lane >> 4) << 3;                   // k col half (0/8)
    int b_ro = (lane & 7) | (((lane >> 4) & 1) << 3);   // n-row within 16
    int b_co = ((lane >> 3) & 1) << 3;             // k col half (0/8)

    float acc[2][NT][4];
#pragma unroll
    for (int i = 0; i < 2; i++)
#pragma unroll
        for (int j = 0; j < NT; j++)
#pragma unroll
            for (int q = 0; q < 4; q++) acc[i][j][q] = 0.f;

    auto load_stage = [&](int s, int kt) {
        uint32_t sb = smb + (uint32_t)s * (STG * 2);
#pragma unroll 4
        for (int i = tid; i < (256 + 2 * BN) * 4; i += 256) {
            int row = i >> 2, seg = (i & 3) << 3;
            const bf16* src; uint32_t toff; int r;
            if (row < 256) {
                r = row & 127;
                src  = (row < 128 ? Ah : Al) + (long)(bm + r) * lda + kt + seg;
                toff = (row < 128) ? 0u : (uint32_t)AST;
            } else {
                int rb = row - 256;
                r = rb & (BN - 1);
                src  = (rb < BN ? Bh : Bl) + (long)(bn + r) * ldb + kt + seg;
                toff = (rb < BN) ? (uint32_t)(2 * AST) : (uint32_t)(2 * AST + BST);
            }
            uint32_t dst = sb + (toff + (uint32_t)(r * KS + seg)) * 2u;
            CPA16(dst, src);
        }
        CPA_COMMIT();
    };

    const int NC = K >> 5;                 // BK = 32
    load_stage(0, 0);

    for (int c = 0; c < NC; c++) {
        int s = c & 1;
        if (c + 1 < NC) { load_stage(s ^ 1, (c + 1) << 5); CPA_WAIT1(); }
        else            { CPA_WAIT0(); }
        __syncthreads();

        uint32_t sbase = smb + (uint32_t)(s * STG) * 2u;
        uint32_t uAh = sbase;
        uint32_t uAl = sbase + (uint32_t)AST * 2u;
        uint32_t uBh = sbase + (uint32_t)(2 * AST) * 2u;
        uint32_t uBl = uBh + (uint32_t)BST * 2u;

#pragma unroll
        for (int ks = 0; ks < 2; ks++) {
            int k0 = ks * 16;
            unsigned aH[2][4], aL[2][4];
#pragma unroll
            for (int mt = 0; mt < 2; mt++) {
                uint32_t ao = (uint32_t)(((mb + mt * 16 + a_ro) * KS + k0 + a_co) * 2);
                ldsm4(aH[mt], uAh + ao);
                ldsm4(aL[mt], uAl + ao);
            }
#pragma unroll
            for (int nt = 0; nt < NT; nt += 2) {
                unsigned bH[4], bL[4];
                uint32_t bo = (uint32_t)(((nb + nt * 8 + b_ro) * KS + k0 + b_co) * 2);
                ldsm4(bH, uBh + bo);
                ldsm4(bL, uBl + bo);
#pragma unroll
                for (int mt = 0; mt < 2; mt++) {
                    mma16816(acc[mt][nt],     aH[mt], bH);       // hi*hi
                    mma16816(acc[mt][nt],     aH[mt], bL);       // hi*lo
                    mma16816(acc[mt][nt],     aL[mt], bH);       // lo*hi
                    mma16816(acc[mt][nt + 1], aH[mt], bH + 2);
                    mma16816(acc[mt][nt + 1], aH[mt], bL + 2);
                    mma16816(acc[mt][nt + 1], aL[mt], bH + 2);
                }
            }
        }
        __syncthreads();
    }

    // ---- epilogue ----
#pragma unroll
    for (int mt = 0; mt < 2; mt++) {
#pragma unroll
        for (int nt = 0; nt < NT; nt++) {
            int gm = bm + mb + mt * 16 + lr;
            int gn = bn + nb + nt * 8 + lc;
            float v0 = acc[mt][nt][0] * alpha;
            float v1 = acc[mt][nt][1] * alpha;
            float v2 = acc[mt][nt][2] * alpha;
            float v3 = acc[mt][nt][3] * alpha;
            if (bias) {
                float b0 = bias[gn], b1 = bias[gn + 1];
                v0 += b0; v1 += b1; v2 += b0; v3 += b1;
            }
            if (relu) {
                v0 = fmaxf(v0, 0.f); v1 = fmaxf(v1, 0.f);
                v2 = fmaxf(v2, 0.f); v3 = fmaxf(v3, 0.f);
            }
            long o0 = cbase + (long)gm * ldc + gn;
            long o1 = cbase + (long)(gm + 8) * ldc + gn;
            if (mode == 0) {
                float2 r0; r0.x = v0; r0.y = v1;
                float2 r1; r1.x = v2; r1.y = v3;
                *(float2*)(Cf + o0) = r0;
                *(float2*)(Cf + o1) = r1;
            } else {
                bf16 h0, l0, h1, l1;
                split2(v0, h0, l0); split2(v1, h1, l1);
                *(bf162*)(Chi + o0) = __halves2bfloat162(h0, h1);
                *(bf162*)(Clo + o0) = __halves2bfloat162(l0, l1);
                split2(v2, h0, l0); split2(v3, h1, l1);
                *(bf162*)(Chi + o1) = __halves2bfloat162(h0, h1);
                *(bf162*)(Clo + o1) = __halves2bfloat162(l0, l1);
            }
        }
    }
}

// ---------------- softmax over rows of 512 -> split bf16 --------------------
__global__ void softmax512(const float* __restrict__ S,
                           bf16* __restrict__ Phi, bf16* __restrict__ Plo) {
    const float* p = S + (long)blockIdx.x * 512;
    int t = threadIdx.x;
    float x0 = p[t], x1 = p[t + 256];
    __shared__ float red[256];
    red[t] = fmaxf(x0, x1); __syncthreads();
    for (int s = 128; s > 0; s >>= 1) {
        if (t < s) red[t] = fmaxf(red[t], red[t + s]);
        __syncthreads();
    }
    float m = red[0]; __syncthreads();
    float e0 = expf(x0 - m), e1 = expf(x1 - m);
    red[t] = e0 + e1; __syncthreads();
    for (int s = 128; s > 0; s >>= 1) {
        if (t < s) red[t] += red[t + s];
        __syncthreads();
    }
    float inv = 1.f / red[0];
    long o = (long)blockIdx.x * 512 + t;
    bf16 h, l;
    split2(e0 * inv, h, l); Phi[o] = h;       Plo[o] = l;
    split2(e1 * inv, h, l); Phi[o + 256] = h; Plo[o + 256] = l;
}

// ---------------- fused residual + LayerNorm (+ split outputs) --------------
__global__ void add_ln(const float* __restrict__ X, const float* __restrict__ R,
                       const float* __restrict__ g, const float* __restrict__ b,
                       float* __restrict__ Y, bf16* __restrict__ Yhi, bf16* __restrict__ Ylo)
{
    long row = blockIdx.x;
    const float* x = X + row * EDIM;
    const float* r = R + row * EDIM;
    int t = threadIdx.x;
    float v[4];
#pragma unroll
    for (int i = 0; i < 4; i++) v[i] = x[t + i*256] + r[t + i*256];
    __shared__ float red[256];
    red[t] = v[0] + v[1] + v[2] + v[3]; __syncthreads();
    for (int s = 128; s > 0; s >>= 1) { if (t < s) red[t] += red[t+s]; __syncthreads(); }
    float mean = red[0] * (1.f / EDIM); __syncthreads();
    float q = 0.f;
#pragma unroll
    for (int i = 0; i < 4; i++) { float d = v[i] - mean; q = fmaf(d, d, q); }
    red[t] = q; __syncthreads();
    for (int s = 128; s > 0; s >>= 1) { if (t < s) red[t] += red[t+s]; __syncthreads(); }
    float inv = rsqrtf(red[0] * (1.f / EDIM) + 1e-5f);
#pragma unroll
    for (int i = 0; i < 4; i++) {
        int c = t + i*256;
        float y = (v[i] - mean) * inv * g[c] + b[c];
        Y[row * EDIM + c] = y;
        bf16 h, l; split2(y, h, l);
        Yhi[row * EDIM + c] = h;
        Ylo[row * EDIM + c] = l;
    }
}

// ---------------- classifier + loss ------------------------------------------
__global__ void classify(const float* __restrict__ Aout, const float* __restrict__ cw,
                         const float* __restrict__ cb, const int* __restrict__ labels,
                         const int* __restrict__ maskA, const int* __restrict__ cand,
                         float* __restrict__ outp, float* __restrict__ part)
{
    int warp = threadIdx.x >> 5, lane = threadIdx.x & 31;
    int row = blockIdx.x * 8 + warp;
    const float* a = Aout + (long)row * EDIM;
    float d0 = 0.f, d1 = 0.f;
    for (int e = lane; e < EDIM; e += 32) {
        float av = a[e];
        d0 = fmaf(av, cw[e], d0);
        d1 = fmaf(av, cw[EDIM + e], d1);
    }
#pragma unroll
    for (int o = 16; o > 0; o >>= 1) {
        d0 += __shfl_down_sync(0xffffffffu, d0, o);
        d1 += __shfl_down_sync(0xffffffffu, d1, o);
    }
    __shared__ float pw[8][2];
    if (lane == 0) {
        float e0 = d0 + cb[0], e1 = d1 + cb[1];
        int lb = labels[row];
        float mx = fmaxf(e0, e1);
        float lse = mx + logf(expf(e0 - mx) + expf(e1 - mx));
        float ce = lse - ((lb == 1) ? e1 : e0);
        float w = (lb == 1) ? 5.0f : 1.0f;
        float valid = (maskA[row] == 1) ? 1.0f : 0.0f;
        pw[warp][0] = ce * w * valid;
        pw[warp][1] = valid;
        int pred1 = (e1 > e0) ? 1 : 0;
        outp[1 + row] = ((cand[row] == 1) && pred1) ? 1.0f : 0.0f;
    }
    __syncthreads();
    if (threadIdx.x == 0) {
        float s0 = 0.f, s1 = 0.f;
#pragma unroll
        for (int i = 0; i < 8; i++) { s0 += pw[i][0]; s1 += pw[i][1]; }
        part[blockIdx.x * 2 + 0] = s0;
        part[blockIdx.x * 2 + 1] = s1;
    }
}

__global__ void finalize(const float* __restrict__ part, float* __restrict__ outp) {
    __shared__ float r0[512], r1[512];
    int t = threadIdx.x;
    r0[t] = part[t * 2 + 0];
    r1[t] = part[t * 2 + 1];
    __syncthreads();
    for (int s = 256; s > 0; s >>= 1) {
        if (t < s) { r0[t] += r0[t+s]; r1[t] += r1[t+s]; }
        __syncthreads();
    }
    if (t == 0) outp[0] = r0[0] / fmaxf(r1[0], 1.0f);
}

// ---------------- host orchestration ----------------------------------------
extern "C" void kernel_launch(void* const* d_in, const int* in_sizes, int n_in,
                              void* d_out, int out_size)
{
    const float* enc   = (const float*)d_in[0];
    const float* dsc   = (const float*)d_in[1];
    const int*   maskA = (const int*)  d_in[2];
    const int*   cand  = (const int*)  d_in[3];
    const int*   labels= (const int*)  d_in[4];
    const float* ipw   = (const float*)d_in[5];
    const float* ipb   = (const float*)d_in[6];
    const float* ow    = (const float*)d_in[7];
    const float* ob    = (const float*)d_in[8];
    const float* g1    = (const float*)d_in[9];
    const float* b1    = (const float*)d_in[10];
    const float* W1    = (const float*)d_in[11];
    const float* bb1   = (const float*)d_in[12];
    const float* W2    = (const float*)d_in[13];
    const float* bb2   = (const float*)d_in[14];
    const float* g2    = (const float*)d_in[15];
    const float* b2    = (const float*)d_in[16];
    const float* cw    = (const float*)d_in[17];
    const float* cb    = (const float*)d_in[18];

    float *A, *A1, *TMP, *V, *S, *PART;
    bf16 *Ahi,*Alo,*A1hi,*A1lo,*Dhi,*Dlo,*Qhi,*Qlo,*Khi,*Klo,*VThi,*VTlo;
    bf16 *Phi,*Plo,*CThi,*CTlo,*MIDhi,*MIDlo;
    bf16 *IPWhi,*IPWlo,*OWhi,*OWlo,*W1hi,*W1lo,*W2hi,*W2lo;
    cudaGetSymbolAddress((void**)&A, g_A);     cudaGetSymbolAddress((void**)&A1, g_A1);
    cudaGetSymbolAddress((void**)&TMP, g_TMP); cudaGetSymbolAddress((void**)&V, g_V);
    cudaGetSymbolAddress((void**)&S, g_S);     cudaGetSymbolAddress((void**)&PART, g_PART);
    cudaGetSymbolAddress((void**)&Ahi, g_Ahi); cudaGetSymbolAddress((void**)&Alo, g_Alo);
    cudaGetSymbolAddress((void**)&A1hi, g_A1hi); cudaGetSymbolAddress((void**)&A1lo, g_A1lo);
    cudaGetSymbolAddress((void**)&Dhi, g_Dhi); cudaGetSymbolAddress((void**)&Dlo, g_Dlo);
    cudaGetSymbolAddress((void**)&Qhi, g_Qhi); cudaGetSymbolAddress((void**)&Qlo, g_Qlo);
    cudaGetSymbolAddress((void**)&Khi, g_Khi); cudaGetSymbolAddress((void**)&Klo, g_Klo);
    cudaGetSymbolAddress((void**)&VThi, g_VThi); cudaGetSymbolAddress((void**)&VTlo, g_VTlo);
    cudaGetSymbolAddress((void**)&Phi, g_Phi); cudaGetSymbolAddress((void**)&Plo, g_Plo);
    cudaGetSymbolAddress((void**)&CThi, g_CThi); cudaGetSymbolAddress((void**)&CTlo, g_CTlo);
    cudaGetSymbolAddress((void**)&MIDhi, g_MIDhi); cudaGetSymbolAddress((void**)&MIDlo, g_MIDlo);
    cudaGetSymbolAddress((void**)&IPWhi, g_IPWhi); cudaGetSymbolAddress((void**)&IPWlo, g_IPWlo);
    cudaGetSymbolAddress((void**)&OWhi, g_OWhi); cudaGetSymbolAddress((void**)&OWlo, g_OWlo);
    cudaGetSymbolAddress((void**)&W1hi, g_W1hi); cudaGetSymbolAddress((void**)&W1lo, g_W1lo);
    cudaGetSymbolAddress((void**)&W2hi, g_W2hi); cudaGetSymbolAddress((void**)&W2lo, g_W2lo);

    // dynamic smem: 2 stages of (2*128 + 2*BN) rows * 40 bf16
    const int SMEM128 = 2 * (2*128*40 + 2*128*40) * 2;   // 81920 B
    const int SMEM64  = 2 * (2*128*40 + 2*64*40)  * 2;   // 61440 B
    static int attr_done = 0;
    if (!attr_done) {
        cudaFuncSetAttribute(gemm_bf3<128>, cudaFuncAttributeMaxDynamicSharedMemorySize, SMEM128);
        cudaFuncSetAttribute(gemm_bf3<64>,  cudaFuncAttributeMaxDynamicSharedMemorySize, SMEM64);
        attr_done = 1;
    }

    // ---- per-call splits ----
    int nIPW = LNUM*3*EDIM*EDIM, nOW = LNUM*EDIM*EDIM;
    int nW1 = LNUM*FDIM*EDIM,    nW2 = LNUM*EDIM*FDIM;
    split_f<<<(nIPW+255)/256, 256>>>(ipw, IPWhi, IPWlo, nIPW);
    split_f<<<(nOW +255)/256, 256>>>(ow,  OWhi,  OWlo,  nOW);
    split_f<<<(nW1 +255)/256, 256>>>(W1,  W1hi,  W1lo,  nW1);
    split_f<<<(nW2 +255)/256, 256>>>(W2,  W2hi,  W2lo,  nW2);
    split_f<<<(BDIM*SBK*EDIM+255)/256, 256>>>(dsc, Dhi, Dlo, BDIM*SBK*EDIM);
    split_f<<<(MROWS*EDIM+255)/256, 256>>>(enc, Ahi, Alo, MROWS*EDIM);
    copy_f <<<(MROWS*EDIM+255)/256, 256>>>(enc, A, MROWS*EDIM);

    const float scaleS = 0.125f;   // 1/sqrt(64)
    dim3 gP (EDIM/128, MROWS/128, 1);      // proj / ffn2 / out-proj
    dim3 gF1(FDIM/128, MROWS/128, 1);      // ffn1
    dim3 gS (SBK/128, SAQ/128, BDIM*HNUM); // scores
    dim3 gC (1, SAQ/128, BDIM*HNUM);       // ctx (BN=64)
    dim3 gT (EDIM/32, MROWS/32, 1);
    dim3 bT (32, 8, 1);

    for (int l = 0; l < LNUM; l++) {
        const bf16 *wqh = IPWhi + (long)l*3*EDIM*EDIM, *wql = IPWlo + (long)l*3*EDIM*EDIM;
        const bf16 *wkh = wqh + EDIM*EDIM, *wkl = wql + EDIM*EDIM;
        const bf16 *wvh = wkh + EDIM*EDIM, *wvl = wkl + EDIM*EDIM;
        const float *bq = ipb + (long)l*3*EDIM, *bk = bq + EDIM, *bv = bk + EDIM;

        // Q/K: split-store bf16.  V: fp32 (for transpose_split).
        gemm_bf3<128><<<gP, 256, SMEM128>>>(Ahi, Alo, wqh, wql, bq, 0, Qhi, Qlo,
            EDIM, EDIM, EDIM, EDIM, 0,0,0,0,0,0,1, 1.0f, 1, 0);
        gemm_bf3<128><<<gP, 256, SMEM128>>>(Dhi, Dlo, wkh, wkl, bk, 0, Khi, Klo,
            EDIM, EDIM, EDIM, EDIM, 0,0,0,0,0,0,1, 1.0f, 1, 0);
        gemm_bf3<128><<<gP, 256, SMEM128>>>(Dhi, Dlo, wvh, wvl, bv, V, 0, 0,
            EDIM, EDIM, EDIM, EDIM, 0,0,0,0,0,0,1, 1.0f, 0, 0);
        transpose_split<<<gT, bT>>>(V, VThi, VTlo);

        // scores = scale * Q @ K^T  (per b,h: M=512,N=512,K=64)
        gemm_bf3<128><<<gS, 256, SMEM128>>>(Qhi, Qlo, Khi, Klo, 0, S, 0, 0,
            DHEAD, EDIM, EDIM, SBK,
            (long)SAQ*EDIM, DHEAD, (long)SBK*EDIM, DHEAD,
            (long)HNUM*SAQ*SBK, (long)SAQ*SBK, HNUM, scaleS, 0, 0);

        softmax512<<<BDIM*HNUM*SAQ, 256>>>(S, Phi, Plo);

        // ctx = P @ V  (TN vs VT: per b,h M=512,N=64,K=512), split-store
        gemm_bf3<64><<<gC, 256, SMEM64>>>(Phi, Plo, VThi, VTlo, 0, 0, CThi, CTlo,
            SBK, SBK, MROWS, EDIM,
            (long)HNUM*SAQ*SBK, (long)SAQ*SBK,
            (long)SBK, (long)DHEAD*MROWS,
            (long)SAQ*EDIM, DHEAD, HNUM, 1.0f, 1, 0);

        // attn_out = ctx @ ow^T + ob  -> fp32 TMP
        gemm_bf3<128><<<gP, 256, SMEM128>>>(CThi, CTlo, OWhi + (long)l*EDIM*EDIM,
            OWlo + (long)l*EDIM*EDIM, ob + (long)l*EDIM, TMP, 0, 0,
            EDIM, EDIM, EDIM, EDIM, 0,0,0,0,0,0,1, 1.0f, 0, 0);

        add_ln<<<MROWS, 256>>>(A, TMP, g1 + (long)l*EDIM, b1 + (long)l*EDIM,
                               A1, A1hi, A1lo);

        // mid = relu(A1 @ W1^T + b1) -> split bf16
        gemm_bf3<128><<<gF1, 256, SMEM128>>>(A1hi, A1lo, W1hi + (long)l*FDIM*EDIM,
            W1lo + (long)l*FDIM*EDIM, bb1 + (long)l*FDIM, 0, MIDhi, MIDlo,
            EDIM, EDIM, EDIM, FDIM, 0,0,0,0,0,0,1, 1.0f, 1, 1);

        // ff = mid @ W2^T + b2 -> fp32 TMP
        gemm_bf3<128><<<gP, 256, SMEM128>>>(MIDhi, MIDlo, W2hi + (long)l*EDIM*FDIM,
            W2lo + (long)l*EDIM*FDIM, bb2 + (long)l*EDIM, TMP, 0, 0,
            FDIM, FDIM, FDIM, EDIM, 0,0,0,0,0,0,1, 1.0f, 0, 0);

        add_ln<<<MROWS, 256>>>(A1, TMP, g2 + (long)l*EDIM, b2 + (long)l*EDIM,
                               A, Ahi, Alo);
    }

    classify<<<MROWS/8, 256>>>(A, cw, cb, labels, maskA, cand, (float*)d_out, PART);
    finalize<<<1, 512>>>(PART, (float*)d_out);
}

// round 7
// speedup vs baseline: 1.6022x; 1.1069x over previous
#include <cuda_runtime.h>
#include <cuda_bf16.h>
#include <math.h>
#include <stdint.h>

// Problem dims
#define LNUM 9
#define BDIM 8
#define SAQ 512
#define SBK 512
#define EDIM 1024
#define HNUM 16
#define DHEAD 64
#define FDIM 4096
#define MROWS (BDIM*SAQ)          // 4096

typedef __nv_bfloat16 bf16;
typedef __nv_bfloat162 bf162;

// ---------------- scratch (device globals) ----------------------------------
__device__ float g_A  [MROWS*EDIM];
__device__ float g_A1 [MROWS*EDIM];
__device__ float g_TMP[MROWS*EDIM];
__device__ float g_V  [MROWS*EDIM];
__device__ float g_S  [(long)BDIM*HNUM*SAQ*SBK];
__device__ float g_PART[1024];

__device__ bf16 g_Ahi [MROWS*EDIM],  g_Alo [MROWS*EDIM];
__device__ bf16 g_A1hi[MROWS*EDIM],  g_A1lo[MROWS*EDIM];
__device__ bf16 g_Dhi [BDIM*SBK*EDIM], g_Dlo [BDIM*SBK*EDIM];
__device__ bf16 g_Qhi [MROWS*EDIM],  g_Qlo [MROWS*EDIM];
__device__ bf16 g_Khi [MROWS*EDIM],  g_Klo [MROWS*EDIM];
__device__ bf16 g_VThi[EDIM*MROWS],  g_VTlo[EDIM*MROWS];
__device__ bf16 g_Phi [(long)BDIM*HNUM*SAQ*SBK], g_Plo[(long)BDIM*HNUM*SAQ*SBK];
__device__ bf16 g_CThi[MROWS*EDIM],  g_CTlo[MROWS*EDIM];
__device__ bf16 g_MIDhi[(long)MROWS*FDIM], g_MIDlo[(long)MROWS*FDIM];
__device__ bf16 g_IPWhi[LNUM*3*EDIM*EDIM], g_IPWlo[LNUM*3*EDIM*EDIM];
__device__ bf16 g_OWhi [LNUM*EDIM*EDIM],   g_OWlo [LNUM*EDIM*EDIM];
__device__ bf16 g_W1hi [(long)LNUM*FDIM*EDIM], g_W1lo[(long)LNUM*FDIM*EDIM];
__device__ bf16 g_W2hi [(long)LNUM*EDIM*FDIM], g_W2lo[(long)LNUM*EDIM*FDIM];

// ---------------- helpers ----------------------------------------------------
__device__ __forceinline__ void split2(float v, bf16& h, bf16& l) {
    h = __float2bfloat16(v);
    l = __float2bfloat16(v - __bfloat162float(h));
}
__device__ __forceinline__ unsigned pack2h(bf16 a, bf16 b) {
    return (uint32_t)__bfloat16_as_ushort(a) | ((uint32_t)__bfloat16_as_ushort(b) << 16);
}

__device__ __forceinline__ uint32_t smem_u32(const void* p) {
    uint32_t a;
    asm("{ .reg .u64 t; cvta.to.shared.u64 t, %1; cvt.u32.u64 %0, t; }"
        : "=r"(a) : "l"(p));
    return a;
}

#define CPA16(dst, src) \
    asm volatile("cp.async.cg.shared.global [%0], [%1], 16;" :: "r"(dst), "l"(src))
#define CPA_COMMIT() asm volatile("cp.async.commit_group;" ::: "memory")
#define CPA_WAIT1()  asm volatile("cp.async.wait_group 1;" ::: "memory")
#define CPA_WAIT0()  asm volatile("cp.async.wait_group 0;" ::: "memory")

__device__ __forceinline__ void ldsm4(unsigned* r, uint32_t addr) {
    asm volatile("ldmatrix.sync.aligned.m8n8.x4.shared.b16 {%0,%1,%2,%3}, [%4];"
        : "=r"(r[0]), "=r"(r[1]), "=r"(r[2]), "=r"(r[3]) : "r"(addr));
}

// vectorized copy / split (4 elems per thread)
__global__ void copy_f4(const float4* __restrict__ src, float4* __restrict__ dst, int n4) {
    int i = blockIdx.x * blockDim.x + threadIdx.x;
    if (i < n4) dst[i] = src[i];
}

__global__ void split_f4(const float4* __restrict__ src, uint2* __restrict__ hi,
                         uint2* __restrict__ lo, int n4) {
    int i = blockIdx.x * blockDim.x + threadIdx.x;
    if (i < n4) {
        float4 v = src[i];
        bf16 h0,l0,h1,l1,h2,l2,h3,l3;
        split2(v.x,h0,l0); split2(v.y,h1,l1); split2(v.z,h2,l2); split2(v.w,h3,l3);
        uint2 H; H.x = pack2h(h0,h1); H.y = pack2h(h2,h3);
        uint2 L; L.x = pack2h(l0,l1); L.y = pack2h(l2,l3);
        hi[i] = H; lo[i] = L;
    }
}

// V [4096][1024] f32 -> VT [1024][4096] split bf16
__global__ void transpose_split(const float* __restrict__ V,
                                bf16* __restrict__ VThi, bf16* __restrict__ VTlo) {
    __shared__ float t[32][33];
    int bx = blockIdx.x * 32, by = blockIdx.y * 32;
    int tx = threadIdx.x, ty = threadIdx.y;
#pragma unroll
    for (int i = 0; i < 4; i++)
        t[ty + i*8][tx] = V[(long)(by + ty + i*8) * EDIM + bx + tx];
    __syncthreads();
#pragma unroll
    for (int i = 0; i < 4; i++) {
        float v = t[tx][ty + i*8];
        bf16 h, l; split2(v, h, l);
        long o = (long)(bx + ty + i*8) * MROWS + by + tx;
        VThi[o] = h; VTlo[o] = l;
    }
}

__device__ __forceinline__ void mma16816(float* d, const unsigned* a, const unsigned* b) {
    asm volatile(
        "mma.sync.aligned.m16n8k16.row.col.f32.bf16.bf16.f32 "
        "{%0,%1,%2,%3},{%4,%5,%6,%7},{%8,%9},{%0,%1,%2,%3};"
        : "+f"(d[0]), "+f"(d[1]), "+f"(d[2]), "+f"(d[3])
        : "r"(a[0]), "r"(a[1]), "r"(a[2]), "r"(a[3]), "r"(b[0]), "r"(b[1]));
}

// ---------------- bf16x3 warp-MMA GEMM (TN), cp.async + ldmatrix -------------
// (unchanged from R6 winner)
template<int BN>
__global__ void __launch_bounds__(256, 2) gemm_bf3(
    const bf16* __restrict__ Ahi_g, const bf16* __restrict__ Alo_g,
    const bf16* __restrict__ Bhi_g, const bf16* __restrict__ Blo_g,
    const float* __restrict__ bias,
    float* __restrict__ Cf, bf16* __restrict__ Chi, bf16* __restrict__ Clo,
    int K, int lda, int ldb, int ldc,
    long sAb, long sAh, long sBb, long sBh, long sCb, long sCh, int nH,
    float alpha, int mode, int relu)
{
    constexpr int KS  = 40;
    constexpr int AST = 128 * KS;
    constexpr int BST = BN * KS;
    constexpr int STG = 2 * AST + 2 * BST;
    constexpr int NT  = BN / 16;

    extern __shared__ bf16 sm[];
    uint32_t smb = smem_u32(sm);

    int bz = blockIdx.z;
    int bb = bz / nH, hh = bz % nH;
    const bf16* Ah = Ahi_g + bb * sAb + hh * sAh;
    const bf16* Al = Alo_g + bb * sAb + hh * sAh;
    const bf16* Bh = Bhi_g + bb * sBb + hh * sBh;
    const bf16* Bl = Blo_g + bb * sBb + hh * sBh;
    long cbase = bb * sCb + hh * sCh;

    int bm = blockIdx.y * 128, bn = blockIdx.x * BN;
    int tid = threadIdx.x;
    int wid = tid >> 5, lane = tid & 31;
    int wm = wid & 3, wn = wid >> 2;
    int mb = wm * 32, nb = wn * (BN / 2);
    int lr = lane >> 2, lc = (lane & 3) * 2;

    int a_ro = lane & 15;
    int a_co = (lane >> 4) << 3;
    int b_ro = (lane & 7) | (((lane >> 4) & 1) << 3);
    int b_co = ((lane >> 3) & 1) << 3;

    float acc[2][NT][4];
#pragma unroll
    for (int i = 0; i < 2; i++)
#pragma unroll
        for (int j = 0; j < NT; j++)
#pragma unroll
            for (int q = 0; q < 4; q++) acc[i][j][q] = 0.f;

    auto load_stage = [&](int s, int kt) {
        uint32_t sb = smb + (uint32_t)s * (STG * 2);
#pragma unroll 4
        for (int i = tid; i < (256 + 2 * BN) * 4; i += 256) {
            int row = i >> 2, seg = (i & 3) << 3;
            const bf16* src; uint32_t toff; int r;
            if (row < 256) {
                r = row & 127;
                src  = (row < 128 ? Ah : Al) + (long)(bm + r) * lda + kt + seg;
                toff = (row < 128) ? 0u : (uint32_t)AST;
            } else {
                int rb = row - 256;
                r = rb & (BN - 1);
                src  = (rb < BN ? Bh : Bl) + (long)(bn + r) * ldb + kt + seg;
                toff = (rb < BN) ? (uint32_t)(2 * AST) : (uint32_t)(2 * AST + BST);
            }
            uint32_t dst = sb + (toff + (uint32_t)(r * KS + seg)) * 2u;
            CPA16(dst, src);
        }
        CPA_COMMIT();
    };

    const int NC = K >> 5;
    load_stage(0, 0);

    for (int c = 0; c < NC; c++) {
        int s = c & 1;
        if (c + 1 < NC) { load_stage(s ^ 1, (c + 1) << 5); CPA_WAIT1(); }
        else            { CPA_WAIT0(); }
        __syncthreads();

        uint32_t sbase = smb + (uint32_t)(s * STG) * 2u;
        uint32_t uAh = sbase;
        uint32_t uAl = sbase + (uint32_t)AST * 2u;
        uint32_t uBh = sbase + (uint32_t)(2 * AST) * 2u;
        uint32_t uBl = uBh + (uint32_t)BST * 2u;

#pragma unroll
        for (int ks = 0; ks < 2; ks++) {
            int k0 = ks * 16;
            unsigned aH[2][4], aL[2][4];
#pragma unroll
            for (int mt = 0; mt < 2; mt++) {
                uint32_t ao = (uint32_t)(((mb + mt * 16 + a_ro) * KS + k0 + a_co) * 2);
                ldsm4(aH[mt], uAh + ao);
                ldsm4(aL[mt], uAl + ao);
            }
#pragma unroll
            for (int nt = 0; nt < NT; nt += 2) {
                unsigned bH[4], bL[4];
                uint32_t bo = (uint32_t)(((nb + nt * 8 + b_ro) * KS + k0 + b_co) * 2);
                ldsm4(bH, uBh + bo);
                ldsm4(bL, uBl + bo);
#pragma unroll
                for (int mt = 0; mt < 2; mt++) {
                    mma16816(acc[mt][nt],     aH[mt], bH);
                    mma16816(acc[mt][nt],     aH[mt], bL);
                    mma16816(acc[mt][nt],     aL[mt], bH);
                    mma16816(acc[mt][nt + 1], aH[mt], bH + 2);
                    mma16816(acc[mt][nt + 1], aH[mt], bL + 2);
                    mma16816(acc[mt][nt + 1], aL[mt], bH + 2);
                }
            }
        }
        __syncthreads();
    }

#pragma unroll
    for (int mt = 0; mt < 2; mt++) {
#pragma unroll
        for (int nt = 0; nt < NT; nt++) {
            int gm = bm + mb + mt * 16 + lr;
            int gn = bn + nb + nt * 8 + lc;
            float v0 = acc[mt][nt][0] * alpha;
            float v1 = acc[mt][nt][1] * alpha;
            float v2 = acc[mt][nt][2] * alpha;
            float v3 = acc[mt][nt][3] * alpha;
            if (bias) {
                float b0 = bias[gn], b1 = bias[gn + 1];
                v0 += b0; v1 += b1; v2 += b0; v3 += b1;
            }
            if (relu) {
                v0 = fmaxf(v0, 0.f); v1 = fmaxf(v1, 0.f);
                v2 = fmaxf(v2, 0.f); v3 = fmaxf(v3, 0.f);
            }
            long o0 = cbase + (long)gm * ldc + gn;
            long o1 = cbase + (long)(gm + 8) * ldc + gn;
            if (mode == 0) {
                float2 r0; r0.x = v0; r0.y = v1;
                float2 r1; r1.x = v2; r1.y = v3;
                *(float2*)(Cf + o0) = r0;
                *(float2*)(Cf + o1) = r1;
            } else {
                bf16 h0, l0, h1, l1;
                split2(v0, h0, l0); split2(v1, h1, l1);
                *(bf162*)(Chi + o0) = __halves2bfloat162(h0, h1);
                *(bf162*)(Clo + o0) = __halves2bfloat162(l0, l1);
                split2(v2, h0, l0); split2(v3, h1, l1);
                *(bf162*)(Chi + o1) = __halves2bfloat162(h0, h1);
                *(bf162*)(Clo + o1) = __halves2bfloat162(l0, l1);
            }
        }
    }
}

// ---------------- softmax: warp per row of 512 -> split bf16 -----------------
__global__ void __launch_bounds__(256) softmax512(
    const float* __restrict__ S, bf16* __restrict__ Phi, bf16* __restrict__ Plo)
{
    int warp = threadIdx.x >> 5, lane = threadIdx.x & 31;
    long row = (long)blockIdx.x * 8 + warp;
    const float4* p = (const float4*)(S + row * 512);
    float4 v[4];
    float mx = -1e30f;
#pragma unroll
    for (int j = 0; j < 4; j++) {
        v[j] = p[j * 32 + lane];
        mx = fmaxf(mx, fmaxf(fmaxf(v[j].x, v[j].y), fmaxf(v[j].z, v[j].w)));
    }
#pragma unroll
    for (int o = 16; o > 0; o >>= 1)
        mx = fmaxf(mx, __shfl_xor_sync(0xffffffffu, mx, o));
    float sum = 0.f;
#pragma unroll
    for (int j = 0; j < 4; j++) {
        v[j].x = expf(v[j].x - mx); v[j].y = expf(v[j].y - mx);
        v[j].z = expf(v[j].z - mx); v[j].w = expf(v[j].w - mx);
        sum += (v[j].x + v[j].y) + (v[j].z + v[j].w);
    }
#pragma unroll
    for (int o = 16; o > 0; o >>= 1)
        sum += __shfl_xor_sync(0xffffffffu, sum, o);
    float inv = 1.f / sum;
    uint2* ph = (uint2*)(Phi + row * 512);
    uint2* pl = (uint2*)(Plo + row * 512);
#pragma unroll
    for (int j = 0; j < 4; j++) {
        bf16 h0,l0,h1,l1,h2,l2,h3,l3;
        split2(v[j].x * inv, h0, l0); split2(v[j].y * inv, h1, l1);
        split2(v[j].z * inv, h2, l2); split2(v[j].w * inv, h3, l3);
        uint2 H; H.x = pack2h(h0, h1); H.y = pack2h(h2, h3);
        uint2 L; L.x = pack2h(l0, l1); L.y = pack2h(l2, l3);
        ph[j * 32 + lane] = H;
        pl[j * 32 + lane] = L;
    }
}

// ---------------- fused residual + LayerNorm (+ split outputs) --------------
__global__ void __launch_bounds__(256) add_ln(
    const float* __restrict__ X, const float* __restrict__ R,
    const float* __restrict__ g, const float* __restrict__ b,
    float* __restrict__ Y, bf16* __restrict__ Yhi, bf16* __restrict__ Ylo)
{
    long row = blockIdx.x;
    const float4* x = (const float4*)(X + row * EDIM);
    const float4* r = (const float4*)(R + row * EDIM);
    int t = threadIdx.x, warp = t >> 5, lane = t & 31;
    float4 v = x[t], rr = r[t];
    v.x += rr.x; v.y += rr.y; v.z += rr.z; v.w += rr.w;

    __shared__ float ws[8];
    float s = (v.x + v.y) + (v.z + v.w);
#pragma unroll
    for (int o = 16; o > 0; o >>= 1) s += __shfl_xor_sync(0xffffffffu, s, o);
    if (lane == 0) ws[warp] = s;
    __syncthreads();
    float mean = ((ws[0]+ws[1])+(ws[2]+ws[3])+((ws[4]+ws[5])+(ws[6]+ws[7]))) * (1.f/EDIM);

    float dx = v.x - mean, dy = v.y - mean, dz = v.z - mean, dw = v.w - mean;
    float q = dx*dx + dy*dy + dz*dz + dw*dw;
#pragma unroll
    for (int o = 16; o > 0; o >>= 1) q += __shfl_xor_sync(0xffffffffu, q, o);
    __syncthreads();
    if (lane == 0) ws[warp] = q;
    __syncthreads();
    float var = ((ws[0]+ws[1])+(ws[2]+ws[3])+((ws[4]+ws[5])+(ws[6]+ws[7]))) * (1.f/EDIM);
    float inv = rsqrtf(var + 1e-5f);

    const float4* gg = (const float4*)(g);
    const float4* bb = (const float4*)(b);
    float4 gv = gg[t], bv = bb[t];
    float4 y;
    y.x = dx * inv * gv.x + bv.x;
    y.y = dy * inv * gv.y + bv.y;
    y.z = dz * inv * gv.z + bv.z;
    y.w = dw * inv * gv.w + bv.w;
    ((float4*)(Y + row * EDIM))[t] = y;
    bf16 h0,l0,h1,l1,h2,l2,h3,l3;
    split2(y.x,h0,l0); split2(y.y,h1,l1); split2(y.z,h2,l2); split2(y.w,h3,l3);
    uint2 H; H.x = pack2h(h0,h1); H.y = pack2h(h2,h3);
    uint2 L; L.x = pack2h(l0,l1); L.y = pack2h(l2,l3);
    ((uint2*)(Yhi + row * EDIM))[t] = H;
    ((uint2*)(Ylo + row * EDIM))[t] = L;
}

// ---------------- classifier + loss ------------------------------------------
__global__ void classify(const float* __restrict__ Aout, const float* __restrict__ cw,
                         const float* __restrict__ cb, const int* __restrict__ labels,
                         const int* __restrict__ maskA, const int* __restrict__ cand,
                         float* __restrict__ outp, float* __restrict__ part)
{
    int warp = threadIdx.x >> 5, lane = threadIdx.x & 31;
    int row = blockIdx.x * 8 + warp;
    const float* a = Aout + (long)row * EDIM;
    float d0 = 0.f, d1 = 0.f;
    for (int e = lane; e < EDIM; e += 32) {
        float av = a[e];
        d0 = fmaf(av, cw[e], d0);
        d1 = fmaf(av, cw[EDIM + e], d1);
    }
#pragma unroll
    for (int o = 16; o > 0; o >>= 1) {
        d0 += __shfl_down_sync(0xffffffffu, d0, o);
        d1 += __shfl_down_sync(0xffffffffu, d1, o);
    }
    __shared__ float pw[8][2];
    if (lane == 0) {
        float e0 = d0 + cb[0], e1 = d1 + cb[1];
        int lb = labels[row];
        float mx = fmaxf(e0, e1);
        float lse = mx + logf(expf(e0 - mx) + expf(e1 - mx));
        float ce = lse - ((lb == 1) ? e1 : e0);
        float w = (lb == 1) ? 5.0f : 1.0f;
        float valid = (maskA[row] == 1) ? 1.0f : 0.0f;
        pw[warp][0] = ce * w * valid;
        pw[warp][1] = valid;
        int pred1 = (e1 > e0) ? 1 : 0;
        outp[1 + row] = ((cand[row] == 1) && pred1) ? 1.0f : 0.0f;
    }
    __syncthreads();
    if (threadIdx.x == 0) {
        float s0 = 0.f, s1 = 0.f;
#pragma unroll
        for (int i = 0; i < 8; i++) { s0 += pw[i][0]; s1 += pw[i][1]; }
        part[blockIdx.x * 2 + 0] = s0;
        part[blockIdx.x * 2 + 1] = s1;
    }
}

__global__ void finalize(const float* __restrict__ part, float* __restrict__ outp) {
    __shared__ float r0[512], r1[512];
    int t = threadIdx.x;
    r0[t] = part[t * 2 + 0];
    r1[t] = part[t * 2 + 1];
    __syncthreads();
    for (int s = 256; s > 0; s >>= 1) {
        if (t < s) { r0[t] += r0[t+s]; r1[t] += r1[t+s]; }
        __syncthreads();
    }
    if (t == 0) outp[0] = r0[0] / fmaxf(r1[0], 1.0f);
}

// ---------------- host orchestration ----------------------------------------
extern "C" void kernel_launch(void* const* d_in, const int* in_sizes, int n_in,
                              void* d_out, int out_size)
{
    const float* enc   = (const float*)d_in[0];
    const float* dsc   = (const float*)d_in[1];
    const int*   maskA = (const int*)  d_in[2];
    const int*   cand  = (const int*)  d_in[3];
    const int*   labels= (const int*)  d_in[4];
    const float* ipw   = (const float*)d_in[5];
    const float* ipb   = (const float*)d_in[6];
    const float* ow    = (const float*)d_in[7];
    const float* ob    = (const float*)d_in[8];
    const float* g1    = (const float*)d_in[9];
    const float* b1    = (const float*)d_in[10];
    const float* W1    = (const float*)d_in[11];
    const float* bb1   = (const float*)d_in[12];
    const float* W2    = (const float*)d_in[13];
    const float* bb2   = (const float*)d_in[14];
    const float* g2    = (const float*)d_in[15];
    const float* b2    = (const float*)d_in[16];
    const float* cw    = (const float*)d_in[17];
    const float* cb    = (const float*)d_in[18];

    float *A, *A1, *TMP, *V, *S, *PART;
    bf16 *Ahi,*Alo,*A1hi,*A1lo,*Dhi,*Dlo,*Qhi,*Qlo,*Khi,*Klo,*VThi,*VTlo;
    bf16 *Phi,*Plo,*CThi,*CTlo,*MIDhi,*MIDlo;
    bf16 *IPWhi,*IPWlo,*OWhi,*OWlo,*W1hi,*W1lo,*W2hi,*W2lo;
    cudaGetSymbolAddress((void**)&A, g_A);     cudaGetSymbolAddress((void**)&A1, g_A1);
    cudaGetSymbolAddress((void**)&TMP, g_TMP); cudaGetSymbolAddress((void**)&V, g_V);
    cudaGetSymbolAddress((void**)&S, g_S);     cudaGetSymbolAddress((void**)&PART, g_PART);
    cudaGetSymbolAddress((void**)&Ahi, g_Ahi); cudaGetSymbolAddress((void**)&Alo, g_Alo);
    cudaGetSymbolAddress((void**)&A1hi, g_A1hi); cudaGetSymbolAddress((void**)&A1lo, g_A1lo);
    cudaGetSymbolAddress((void**)&Dhi, g_Dhi); cudaGetSymbolAddress((void**)&Dlo, g_Dlo);
    cudaGetSymbolAddress((void**)&Qhi, g_Qhi); cudaGetSymbolAddress((void**)&Qlo, g_Qlo);
    cudaGetSymbolAddress((void**)&Khi, g_Khi); cudaGetSymbolAddress((void**)&Klo, g_Klo);
    cudaGetSymbolAddress((void**)&VThi, g_VThi); cudaGetSymbolAddress((void**)&VTlo, g_VTlo);
    cudaGetSymbolAddress((void**)&Phi, g_Phi); cudaGetSymbolAddress((void**)&Plo, g_Plo);
    cudaGetSymbolAddress((void**)&CThi, g_CThi); cudaGetSymbolAddress((void**)&CTlo, g_CTlo);
    cudaGetSymbolAddress((void**)&MIDhi, g_MIDhi); cudaGetSymbolAddress((void**)&MIDlo, g_MIDlo);
    cudaGetSymbolAddress((void**)&IPWhi, g_IPWhi); cudaGetSymbolAddress((void**)&IPWlo, g_IPWlo);
    cudaGetSymbolAddress((void**)&OWhi, g_OWhi); cudaGetSymbolAddress((void**)&OWlo, g_OWlo);
    cudaGetSymbolAddress((void**)&W1hi, g_W1hi); cudaGetSymbolAddress((void**)&W1lo, g_W1lo);
    cudaGetSymbolAddress((void**)&W2hi, g_W2hi); cudaGetSymbolAddress((void**)&W2lo, g_W2lo);

    const int SMEM128 = 2 * (2*128*40 + 2*128*40) * 2;   // 81920 B
    const int SMEM64  = 2 * (2*128*40 + 2*64*40)  * 2;   // 61440 B
    static int attr_done = 0;
    if (!attr_done) {
        cudaFuncSetAttribute(gemm_bf3<128>, cudaFuncAttributeMaxDynamicSharedMemorySize, SMEM128);
        cudaFuncSetAttribute(gemm_bf3<64>,  cudaFuncAttributeMaxDynamicSharedMemorySize, SMEM64);
        attr_done = 1;
    }

    // ---- per-call splits (vectorized ×4) ----
    int nIPW = LNUM*3*EDIM*EDIM, nOW = LNUM*EDIM*EDIM;
    int nW1 = LNUM*FDIM*EDIM,    nW2 = LNUM*EDIM*FDIM;
    split_f4<<<(nIPW/4+255)/256, 256>>>((const float4*)ipw, (uint2*)IPWhi, (uint2*)IPWlo, nIPW/4);
    split_f4<<<(nOW /4+255)/256, 256>>>((const float4*)ow,  (uint2*)OWhi,  (uint2*)OWlo,  nOW/4);
    split_f4<<<(nW1 /4+255)/256, 256>>>((const float4*)W1,  (uint2*)W1hi,  (uint2*)W1lo,  nW1/4);
    split_f4<<<(nW2 /4+255)/256, 256>>>((const float4*)W2,  (uint2*)W2hi,  (uint2*)W2lo,  nW2/4);
    split_f4<<<(BDIM*SBK*EDIM/4+255)/256, 256>>>((const float4*)dsc, (uint2*)Dhi, (uint2*)Dlo, BDIM*SBK*EDIM/4);
    split_f4<<<(MROWS*EDIM/4+255)/256, 256>>>((const float4*)enc, (uint2*)Ahi, (uint2*)Alo, MROWS*EDIM/4);
    copy_f4 <<<(MROWS*EDIM/4+255)/256, 256>>>((const float4*)enc, (float4*)A, MROWS*EDIM/4);

    const float scaleS = 0.125f;   // 1/sqrt(64)
    dim3 gP (EDIM/128, MROWS/128, 1);
    dim3 gF1(FDIM/128, MROWS/128, 1);
    dim3 gS (SBK/128, SAQ/128, BDIM*HNUM);
    dim3 gC (1, SAQ/128, BDIM*HNUM);
    dim3 gT (EDIM/32, MROWS/32, 1);
    dim3 bT (32, 8, 1);

    for (int l = 0; l < LNUM; l++) {
        const bf16 *wqh = IPWhi + (long)l*3*EDIM*EDIM, *wql = IPWlo + (long)l*3*EDIM*EDIM;
        const bf16 *wkh = wqh + EDIM*EDIM, *wkl = wql + EDIM*EDIM;
        const bf16 *wvh = wkh + EDIM*EDIM, *wvl = wkl + EDIM*EDIM;
        const float *bq = ipb + (long)l*3*EDIM, *bk = bq + EDIM, *bv = bk + EDIM;

        gemm_bf3<128><<<gP, 256, SMEM128>>>(Ahi, Alo, wqh, wql, bq, 0, Qhi, Qlo,
            EDIM, EDIM, EDIM, EDIM, 0,0,0,0,0,0,1, 1.0f, 1, 0);
        gemm_bf3<128><<<gP, 256, SMEM128>>>(Dhi, Dlo, wkh, wkl, bk, 0, Khi, Klo,
            EDIM, EDIM, EDIM, EDIM, 0,0,0,0,0,0,1, 1.0f, 1, 0);
        gemm_bf3<128><<<gP, 256, SMEM128>>>(Dhi, Dlo, wvh, wvl, bv, V, 0, 0,
            EDIM, EDIM, EDIM, EDIM, 0,0,0,0,0,0,1, 1.0f, 0, 0);
        transpose_split<<<gT, bT>>>(V, VThi, VTlo);

        // scores = scale * Q @ K^T
        gemm_bf3<128><<<gS, 256, SMEM128>>>(Qhi, Qlo, Khi, Klo, 0, S, 0, 0,
            DHEAD, EDIM, EDIM, SBK,
            (long)SAQ*EDIM, DHEAD, (long)SBK*EDIM, DHEAD,
            (long)HNUM*SAQ*SBK, (long)SAQ*SBK, HNUM, scaleS, 0, 0);

        softmax512<<<BDIM*HNUM*SAQ/8, 256>>>(S, Phi, Plo);

        // ctx = P @ V
        gemm_bf3<64><<<gC, 256, SMEM64>>>(Phi, Plo, VThi, VTlo, 0, 0, CThi, CTlo,
            SBK, SBK, MROWS, EDIM,
            (long)HNUM*SAQ*SBK, (long)SAQ*SBK,
            (long)SBK, (long)DHEAD*MROWS,
            (long)SAQ*EDIM, DHEAD, HNUM, 1.0f, 1, 0);

        gemm_bf3<128><<<gP, 256, SMEM128>>>(CThi, CTlo, OWhi + (long)l*EDIM*EDIM,
            OWlo + (long)l*EDIM*EDIM, ob + (long)l*EDIM, TMP, 0, 0,
            EDIM, EDIM, EDIM, EDIM, 0,0,0,0,0,0,1, 1.0f, 0, 0);

        add_ln<<<MROWS, 256>>>(A, TMP, g1 + (long)l*EDIM, b1 + (long)l*EDIM,
                               A1, A1hi, A1lo);

        gemm_bf3<128><<<gF1, 256, SMEM128>>>(A1hi, A1lo, W1hi + (long)l*FDIM*EDIM,
            W1lo + (long)l*FDIM*EDIM, bb1 + (long)l*FDIM, 0, MIDhi, MIDlo,
            EDIM, EDIM, EDIM, FDIM, 0,0,0,0,0,0,1, 1.0f, 1, 1);

        gemm_bf3<128><<<gP, 256, SMEM128>>>(MIDhi, MIDlo, W2hi + (long)l*EDIM*FDIM,
            W2lo + (long)l*EDIM*FDIM, bb2 + (long)l*EDIM, TMP, 0, 0,
            FDIM, FDIM, FDIM, EDIM, 0,0,0,0,0,0,1, 1.0f, 0, 0);

        add_ln<<<MROWS, 256>>>(A1, TMP, g2 + (long)l*EDIM, b2 + (long)l*EDIM,
                               A, Ahi, Alo);
    }

    classify<<<MROWS/8, 256>>>(A, cw, cb, labels, maskA, cand, (float*)d_out, PART);
    finalize<<<1, 512>>>(PART, (float*)d_out);
}